// round 3
// baseline (speedup 1.0000x reference)
#include <cuda_runtime.h>

// ---- scratch (no allocations allowed) ----
#define NBLOCKS_P1 1184            // 148 SMs * 8
#define THREADS    256

__device__ float g_partials[NBLOCKS_P1];
__device__ float g_inv;

// ---------------- pass 1: sum(exp(x)) partials ----------------
__global__ __launch_bounds__(THREADS) void softmax_sum_kernel(
    const float4* __restrict__ in, int n4)
{
    float s = 0.0f;
    int stride = gridDim.x * blockDim.x;
    for (int i = blockIdx.x * blockDim.x + threadIdx.x; i < n4; i += stride) {
        float4 v = in[i];
        s += __expf(v.x) + __expf(v.y) + __expf(v.z) + __expf(v.w);
    }
    // warp tree reduce
    #pragma unroll
    for (int off = 16; off > 0; off >>= 1)
        s += __shfl_xor_sync(0xffffffffu, s, off);

    __shared__ float warp_sums[THREADS / 32];
    int lane = threadIdx.x & 31;
    int wid  = threadIdx.x >> 5;
    if (lane == 0) warp_sums[wid] = s;
    __syncthreads();

    if (wid == 0) {
        float t = (lane < (THREADS / 32)) ? warp_sums[lane] : 0.0f;
        #pragma unroll
        for (int off = 16; off > 0; off >>= 1)
            t += __shfl_xor_sync(0xffffffffu, t, off);
        if (lane == 0) g_partials[blockIdx.x] = t;
    }
}

// ---------------- pass 2: reduce partials -> 1/sum ----------------
__global__ __launch_bounds__(1024) void softmax_finalize_kernel()
{
    float s = 0.0f;
    for (int i = threadIdx.x; i < NBLOCKS_P1; i += 1024)
        s += g_partials[i];

    #pragma unroll
    for (int off = 16; off > 0; off >>= 1)
        s += __shfl_xor_sync(0xffffffffu, s, off);

    __shared__ float warp_sums[32];
    int lane = threadIdx.x & 31;
    int wid  = threadIdx.x >> 5;
    if (lane == 0) warp_sums[wid] = s;
    __syncthreads();

    if (wid == 0) {
        float t = (lane < 32) ? warp_sums[lane] : 0.0f;
        #pragma unroll
        for (int off = 16; off > 0; off >>= 1)
            t += __shfl_xor_sync(0xffffffffu, t, off);
        if (lane == 0) g_inv = 1.0f / t;
    }
}

// ---------------- pass 3: out = exp(x) * inv ----------------
__global__ __launch_bounds__(THREADS) void softmax_scale_kernel(
    const float4* __restrict__ in, float4* __restrict__ out, int n4)
{
    float inv = g_inv;
    int stride = gridDim.x * blockDim.x;
    for (int i = blockIdx.x * blockDim.x + threadIdx.x; i < n4; i += stride) {
        float4 v = in[i];
        float4 r;
        r.x = __expf(v.x) * inv;
        r.y = __expf(v.y) * inv;
        r.z = __expf(v.z) * inv;
        r.w = __expf(v.w) * inv;
        out[i] = r;
    }
}

extern "C" void kernel_launch(void* const* d_in, const int* in_sizes, int n_in,
                              void* d_out, int out_size)
{
    const float4* in  = (const float4*)d_in[0];
    float4*       out = (float4*)d_out;
    int n  = in_sizes[0];
    int n4 = n >> 2;   // N = 33554432, divisible by 4

    softmax_sum_kernel<<<NBLOCKS_P1, THREADS>>>(in, n4);
    softmax_finalize_kernel<<<1, 1024>>>();
    softmax_scale_kernel<<<2368, THREADS>>>(in, out, n4);
}